// round 3
// baseline (speedup 1.0000x reference)
#include <cuda_runtime.h>
#include <cstdint>

#define BB 8
#define CC 64
#define OO 64
#define HH 96
#define WW 96
#define HW (HH*WW)          // 9216
#define K2 9
#define NOFF 18             // 2*K*K

typedef unsigned long long ull;

#define PACKF2(d, lo, hi) asm("mov.b64 %0, {%1,%2};" : "=l"(d) : "f"(lo), "f"(hi))
#define UNPKF2(lo, hi, s) asm("mov.b64 {%0,%1}, %2;" : "=f"(lo), "=f"(hi) : "l"(s))
#define FMA2(d, a, b, c)  asm("fma.rn.f32x2 %0, %1, %2, %3;" : "=l"(d) : "l"(a), "l"(b), "l"(c))

// ---------------- scratch ----------------------------------------------------
__device__ float g_xt[BB * HW * CC];          // x in NHWC (~18.9 MB)
__device__ float g_offs[BB * HW * NOFF];      // offsets, pixel-major (~5.3 MB)
__device__ float g_wt[K2 * CC * OO];          // conv_w as [k][c][o] (147 KB)
__device__ float g_owt[CC * K2 * 20];         // offset_w as [c][tap][j pad 20]

// ---------------- kernel T1: NCHW -> NHWC transpose -------------------------
__global__ void transpose_x_kernel(const float* __restrict__ x, float* __restrict__ xt) {
    __shared__ float tile[32][33];
    int blk = blockIdx.x;            // 8 * 2 * 288
    int pt  = blk % 288;
    int ct  = (blk / 288) & 1;
    int b   = blk / 576;
    int lx = threadIdx.x & 31, ly = threadIdx.x >> 5;
    int p0 = pt * 32, c0 = ct * 32;
    const float* xb = x + (size_t)(b * CC + c0) * HW + p0;
#pragma unroll
    for (int i = 0; i < 4; i++) {
        int cc = ly + 8 * i;
        tile[cc][lx] = xb[(size_t)cc * HW + lx];
    }
    __syncthreads();
    float* xo = xt + (size_t)(b * HW + p0) * CC + c0;
#pragma unroll
    for (int i = 0; i < 4; i++) {
        int pp = ly + 8 * i;
        xo[(size_t)pp * CC + lx] = tile[lx][pp];
    }
}

// ---------------- kernel T2: weight re-layouts -------------------------------
__global__ void build_weights_kernel(const float* __restrict__ cw,
                                     const float* __restrict__ ow,
                                     float* __restrict__ wt,
                                     float* __restrict__ owt) {
    int idx = blockIdx.x * 256 + threadIdx.x;
    if (idx < OO * CC * K2) {            // conv_w (o,c,k) -> wt[k][c][o]
        int o = idx / (CC * K2);
        int r = idx % (CC * K2);
        int c = r / K2;
        int k = r % K2;
        wt[(k * CC + c) * OO + o] = cw[idx];
    }
    if (idx < NOFF * CC * K2) {          // offset_w (j,c,k) -> owt[c][k][j] (stride 20)
        int j = idx / (CC * K2);
        int r = idx % (CC * K2);
        int c = r / K2;
        int k = r % K2;
        owt[(c * K2 + k) * 20 + j] = ow[idx];
    }
}

// ---------------- kernel 1: offset conv (f32x2), 1 px / thread --------------
__global__ void __launch_bounds__(256) offset_conv_kernel(
    const float* __restrict__ x, const float* __restrict__ owt,
    const float* __restrict__ ob, float* __restrict__ offs)
{
    __shared__ float ws[CC * K2 * 20];    // 46080 B
    __shared__ float bs[NOFF];
    int tid = threadIdx.x;
    for (int i = tid; i < CC * K2 * 20; i += 256) ws[i] = owt[i];
    if (tid < NOFF) bs[tid] = ob[tid];
    __syncthreads();

    int flat = blockIdx.x * 256 + tid;     // 0 .. 73727
    int b = flat / HW, p = flat % HW;
    int h = p / WW, w = p % WW;
    const float* x0 = x + (size_t)b * CC * HW;

    ull a0[9];
#pragma unroll
    for (int j = 0; j < 9; j++) a0[j] = 0ull;

    int yy[3], xx[3]; bool vy[3], vx[3];
#pragma unroll
    for (int d = 0; d < 3; d++) {
        yy[d] = h + d - 1; vy[d] = (unsigned)yy[d] < (unsigned)HH;
        xx[d] = w + d - 1; vx[d] = (unsigned)xx[d] < (unsigned)WW;
    }

    for (int c = 0; c < CC; c++) {
        float xv0[9];
        const float* xc0 = x0 + (size_t)c * HW;
#pragma unroll
        for (int dy = 0; dy < 3; dy++)
#pragma unroll
            for (int dx = 0; dx < 3; dx++) {
                int i = dy * 3 + dx;
                bool v = vy[dy] && vx[dx];
                xv0[i] = v ? xc0[yy[dy] * WW + xx[dx]] : 0.f;
            }
#pragma unroll
        for (int i = 0; i < 9; i++) {
            const float* row = ws + (c * K2 + i) * 20;
            ull s0;
            PACKF2(s0, xv0[i], xv0[i]);
#pragma unroll
            for (int j = 0; j < 9; j++) {
                ull wv = *(const ull*)(row + 2 * j);
                FMA2(a0[j], s0, wv, a0[j]);
            }
        }
    }
    float* o0 = offs + (size_t)flat * NOFF;
#pragma unroll
    for (int j = 0; j < 9; j++) {
        float lo, hi;
        UNPKF2(lo, hi, a0[j]);
        *(float2*)(o0 + 2 * j) = make_float2(lo + bs[2 * j], hi + bs[2 * j + 1]);
    }
}

// ---------------- kernel 2: fused sampling + f32x2 GEMM ---------------------
// CTA: 256 threads, tile = 128 px x 64 out. Per thread: 4 px x 8 out.
#define SAMP_ST 68
#define SAMP_SZ (128 * SAMP_ST)          // 8704 floats / buffer
#define WS_SZ   (CC * OO)                // 4096
#define SMEM_FUSED ((2 * SAMP_SZ + 2 * WS_SZ) * 4)   // 102400 B

__device__ __forceinline__ void fill_tap(
    const float* __restrict__ xt_b, const float* __restrict__ offs_b,
    int p0, int tap, float* __restrict__ sbuf, int warp, int lane)
{
    int kdy = tap / 3 - 1, kdx = tap % 3 - 1;
    int c = 2 * lane;
    for (int px = warp; px < 128; px += 8) {
        int p = p0 + px;
        int h = p / WW, w = p - h * WW;
        float2 od = *(const float2*)(offs_b + (size_t)p * NOFF + 2 * tap);
        float py  = (float)(h + kdy) + od.x;
        float pxf = (float)(w + kdx) + od.y;
        float fy = floorf(py), fx = floorf(pxf);
        int y0 = (int)fy, x0 = (int)fx;
        float wy = py - fy, wx = pxf - fx;
        bool vy0 = (unsigned)y0 < (unsigned)HH;
        bool vy1 = (unsigned)(y0 + 1) < (unsigned)HH;
        bool vx0 = (unsigned)x0 < (unsigned)WW;
        bool vx1 = (unsigned)(x0 + 1) < (unsigned)WW;
        const float* base = xt_b + ((ptrdiff_t)y0 * WW + x0) * CC + c;
        float2 z = make_float2(0.f, 0.f);
        float2 g00 = (vy0 && vx0) ? *(const float2*)(base)              : z;
        float2 g01 = (vy0 && vx1) ? *(const float2*)(base + CC)         : z;
        float2 g10 = (vy1 && vx0) ? *(const float2*)(base + WW*CC)      : z;
        float2 g11 = (vy1 && vx1) ? *(const float2*)(base + WW*CC + CC) : z;
        float w00 = (1.f - wy) * (1.f - wx);
        float w01 = (1.f - wy) * wx;
        float w10 = wy * (1.f - wx);
        float w11 = wy * wx;
        float sx = g00.x * w00 + g01.x * w01 + g10.x * w10 + g11.x * w11;
        float sy = g00.y * w00 + g01.y * w01 + g10.y * w10 + g11.y * w11;
        *(float2*)(sbuf + px * SAMP_ST + c) = make_float2(sx, sy);
    }
}

__global__ void __launch_bounds__(256) fused_deform_kernel(
    const float* __restrict__ xt, const float* __restrict__ offs,
    const float* __restrict__ wt, const float* __restrict__ cb,
    float* __restrict__ out)
{
    extern __shared__ float sm[];
    float* samp = sm;                    // 2 * 8704
    float* wsb  = sm + 2 * SAMP_SZ;      // 2 * 4096

    int tid  = threadIdx.x;
    int tx   = tid & 7;                  // out group (8 outs)
    int ty   = tid >> 3;                 // px group (4 contiguous px)
    int warp = tid >> 5;
    int lane = tid & 31;
    int b    = blockIdx.x / 72;
    int p0   = (blockIdx.x % 72) * 128;

    const float* xt_b   = xt   + (size_t)b * HW * CC;
    const float* offs_b = offs + (size_t)b * HW * NOFF;

    ull acc[4][4];
#pragma unroll
    for (int i = 0; i < 4; i++)
#pragma unroll
        for (int j = 0; j < 4; j++) acc[i][j] = 0ull;

    // prologue: tap 0
    {
        const float4* src = (const float4*)(wt);
        float4* dst = (float4*)(wsb);
#pragma unroll
        for (int r = 0; r < 4; r++) dst[tid + 256 * r] = src[tid + 256 * r];
        fill_tap(xt_b, offs_b, p0, 0, samp, warp, lane);
    }

    int txo = tx * 8;
    for (int ck = 0; ck < 9; ck++) {
        __syncthreads();
        int cur = ck & 1, nxt = cur ^ 1;
        if (ck < 8) {
            const float4* src = (const float4*)(wt + (ck + 1) * WS_SZ);
            float4* dst = (float4*)(wsb + nxt * WS_SZ);
#pragma unroll
            for (int r = 0; r < 4; r++) dst[tid + 256 * r] = src[tid + 256 * r];
            fill_tap(xt_b, offs_b, p0, ck + 1, samp + nxt * SAMP_SZ, warp, lane);
        }

        const float* sb = samp + cur * SAMP_SZ + (ty * 4) * SAMP_ST;
        const float* wb = wsb  + cur * WS_SZ;
#pragma unroll 2
        for (int cc = 0; cc < 64; cc += 4) {
            float4 sv[4];
#pragma unroll
            for (int i = 0; i < 4; i++)
                sv[i] = *(const float4*)(sb + i * SAMP_ST + cc);
#pragma unroll
            for (int r = 0; r < 4; r++) {
                float4 wa = *(const float4*)(wb + (cc + r) * 64 + txo);
                float4 wc = *(const float4*)(wb + (cc + r) * 64 + txo + 4);
                ull w0, w1, w2, w3;
                PACKF2(w0, wa.x, wa.y);
                PACKF2(w1, wa.z, wa.w);
                PACKF2(w2, wc.x, wc.y);
                PACKF2(w3, wc.z, wc.w);
#pragma unroll
                for (int i = 0; i < 4; i++) {
                    float s = (r == 0) ? sv[i].x : (r == 1) ? sv[i].y :
                              (r == 2) ? sv[i].z : sv[i].w;
                    ull ss;
                    PACKF2(ss, s, s);
                    FMA2(acc[i][0], ss, w0, acc[i][0]);
                    FMA2(acc[i][1], ss, w1, acc[i][1]);
                    FMA2(acc[i][2], ss, w2, acc[i][2]);
                    FMA2(acc[i][3], ss, w3, acc[i][3]);
                }
            }
        }
    }

    // epilogue: bias + STG.128 (4 contiguous px per thread)
    int p = p0 + ty * 4;
#pragma unroll
    for (int j = 0; j < 4; j++) {
        float bL = cb[txo + 2 * j];
        float bH = cb[txo + 2 * j + 1];
        float4 vlo, vhi;
        float lo, hi;
        UNPKF2(lo, hi, acc[0][j]); vlo.x = lo + bL; vhi.x = hi + bH;
        UNPKF2(lo, hi, acc[1][j]); vlo.y = lo + bL; vhi.y = hi + bH;
        UNPKF2(lo, hi, acc[2][j]); vlo.z = lo + bL; vhi.z = hi + bH;
        UNPKF2(lo, hi, acc[3][j]); vlo.w = lo + bL; vhi.w = hi + bH;
        float* oL = out + (size_t)(b * OO + txo + 2 * j) * HW + p;
        *(float4*)oL = vlo;
        *(float4*)(oL + HW) = vhi;
    }
}

// ---------------- launch ------------------------------------------------------
extern "C" void kernel_launch(void* const* d_in, const int* in_sizes, int n_in,
                              void* d_out, int out_size) {
    const float* x  = (const float*)d_in[0];
    const float* ow = (const float*)d_in[1];
    const float* ob = (const float*)d_in[2];
    const float* cw = (const float*)d_in[3];
    const float* cb = (const float*)d_in[4];
    float* out = (float*)d_out;

    float *xt, *offs, *wt, *owt;
    cudaGetSymbolAddress((void**)&xt,   g_xt);
    cudaGetSymbolAddress((void**)&offs, g_offs);
    cudaGetSymbolAddress((void**)&wt,   g_wt);
    cudaGetSymbolAddress((void**)&owt,  g_owt);

    cudaFuncSetAttribute(fused_deform_kernel,
                         cudaFuncAttributeMaxDynamicSharedMemorySize, SMEM_FUSED);

    transpose_x_kernel<<<4608, 256>>>(x, xt);
    build_weights_kernel<<<144, 256>>>(cw, ow, wt, owt);
    offset_conv_kernel<<<288, 256>>>(x, owt, ob, offs);
    fused_deform_kernel<<<576, 256, SMEM_FUSED>>>(xt, offs, wt, cb, out);
}

// round 4
// speedup vs baseline: 1.1959x; 1.1959x over previous
#include <cuda_runtime.h>
#include <cstdint>

#define BB 8
#define CC 64
#define OO 64
#define HH 96
#define WW 96
#define HW (HH*WW)          // 9216
#define K2 9
#define NOFF 18

typedef unsigned long long ull;

#define PACKF2(d, lo, hi) asm("mov.b64 %0, {%1,%2};" : "=l"(d) : "f"(lo), "f"(hi))
#define UNPKF2(lo, hi, s) asm("mov.b64 {%0,%1}, %2;" : "=f"(lo), "=f"(hi) : "l"(s))
#define FMA2(d, a, b, c)  asm("fma.rn.f32x2 %0, %1, %2, %3;" : "=l"(d) : "l"(a), "l"(b), "l"(c))

// ---------------- scratch ----------------------------------------------------
__device__ float g_xt[BB * HW * CC];          // x in NHWC (~18.9 MB)
__device__ float g_offs[BB * HW * NOFF];      // offsets, pixel-major (~5.3 MB)
__device__ float g_wt[K2 * CC * OO];          // conv_w as [k][c][o]
__device__ float g_owt[CC * K2 * 20];         // offset_w as [c][tap][j pad 20]

// ---------------- kernel T1: NCHW -> NHWC transpose -------------------------
__global__ void transpose_x_kernel(const float* __restrict__ x, float* __restrict__ xt) {
    __shared__ float tile[32][33];
    int blk = blockIdx.x;            // 8 * 2 * 288
    int pt  = blk % 288;
    int ct  = (blk / 288) & 1;
    int b   = blk / 576;
    int lx = threadIdx.x & 31, ly = threadIdx.x >> 5;
    int p0 = pt * 32, c0 = ct * 32;
    const float* xb = x + (size_t)(b * CC + c0) * HW + p0;
#pragma unroll
    for (int i = 0; i < 4; i++) {
        int cc = ly + 8 * i;
        tile[cc][lx] = xb[(size_t)cc * HW + lx];
    }
    __syncthreads();
    float* xo = xt + (size_t)(b * HW + p0) * CC + c0;
#pragma unroll
    for (int i = 0; i < 4; i++) {
        int pp = ly + 8 * i;
        xo[(size_t)pp * CC + lx] = tile[lx][pp];
    }
}

// ---------------- kernel T2: weight re-layouts -------------------------------
__global__ void build_weights_kernel(const float* __restrict__ cw,
                                     const float* __restrict__ ow,
                                     float* __restrict__ wt,
                                     float* __restrict__ owt) {
    int idx = blockIdx.x * 256 + threadIdx.x;
    if (idx < OO * CC * K2) {
        int o = idx / (CC * K2);
        int r = idx % (CC * K2);
        int c = r / K2;
        int k = r % K2;
        wt[(k * CC + c) * OO + o] = cw[idx];
    }
    if (idx < NOFF * CC * K2) {
        int j = idx / (CC * K2);
        int r = idx % (CC * K2);
        int c = r / K2;
        int k = r % K2;
        owt[(c * K2 + k) * 20 + j] = ow[idx];
    }
}

// ---------------- kernel 1: offset conv (f32x2), 1 px / thread --------------
__global__ void __launch_bounds__(256) offset_conv_kernel(
    const float* __restrict__ x, const float* __restrict__ owt,
    const float* __restrict__ ob, float* __restrict__ offs)
{
    __shared__ float ws[CC * K2 * 20];
    __shared__ float bs[NOFF];
    int tid = threadIdx.x;
    for (int i = tid; i < CC * K2 * 20; i += 256) ws[i] = owt[i];
    if (tid < NOFF) bs[tid] = ob[tid];
    __syncthreads();

    int flat = blockIdx.x * 256 + tid;
    int b = flat / HW, p = flat % HW;
    int h = p / WW, w = p % WW;
    const float* x0 = x + (size_t)b * CC * HW;

    ull a0[9];
#pragma unroll
    for (int j = 0; j < 9; j++) a0[j] = 0ull;

    int yy[3], xx[3]; bool vy[3], vx[3];
#pragma unroll
    for (int d = 0; d < 3; d++) {
        yy[d] = h + d - 1; vy[d] = (unsigned)yy[d] < (unsigned)HH;
        xx[d] = w + d - 1; vx[d] = (unsigned)xx[d] < (unsigned)WW;
    }

    for (int c = 0; c < CC; c++) {
        float xv0[9];
        const float* xc0 = x0 + (size_t)c * HW;
#pragma unroll
        for (int dy = 0; dy < 3; dy++)
#pragma unroll
            for (int dx = 0; dx < 3; dx++) {
                int i = dy * 3 + dx;
                bool v = vy[dy] && vx[dx];
                xv0[i] = v ? xc0[yy[dy] * WW + xx[dx]] : 0.f;
            }
#pragma unroll
        for (int i = 0; i < 9; i++) {
            const float* row = ws + (c * K2 + i) * 20;
            ull s0;
            PACKF2(s0, xv0[i], xv0[i]);
#pragma unroll
            for (int j = 0; j < 9; j++) {
                ull wv = *(const ull*)(row + 2 * j);
                FMA2(a0[j], s0, wv, a0[j]);
            }
        }
    }
    float* o0 = offs + (size_t)flat * NOFF;
#pragma unroll
    for (int j = 0; j < 9; j++) {
        float lo, hi;
        UNPKF2(lo, hi, a0[j]);
        *(float2*)(o0 + 2 * j) = make_float2(lo + bs[2 * j], hi + bs[2 * j + 1]);
    }
}

// ---------------- kernel 2: fused sampling + f32x2 GEMM ---------------------
// CTA: 256 threads. Tile 256 px x 64 out; thread tile 8 px (stride 32) x 8 out.
// smem: samp[256][68] single buf + w[64][64] + offs_s[256][18]
#define SAMP_ST 68
#define SAMP_FLOATS (256 * SAMP_ST)                 // 17408
#define SMEM_FUSED ((SAMP_FLOATS + 4096 + 4608) * 4) // 104448 B

__global__ void __launch_bounds__(256, 2) fused_deform_kernel(
    const float* __restrict__ xt, const float* __restrict__ offs,
    const float* __restrict__ wt, const float* __restrict__ cb,
    float* __restrict__ out)
{
    extern __shared__ float sm[];
    float* samp   = sm;                       // 17408 floats
    float* wsb    = sm + SAMP_FLOATS;         // 4096
    float* offs_s = wsb + 4096;               // 4608

    int tid  = threadIdx.x;
    int tx   = tid & 7;                  // out group
    int ty   = tid >> 3;                 // px lane 0..31
    int warp = tid >> 5;
    int lane = tid & 31;
    int b    = blockIdx.x / 36;
    int p0   = (blockIdx.x % 36) * 256;

    const float* xt_b = xt + (size_t)b * HW * CC;

    // stage offsets for 256 px: 4608 floats
    {
        const float4* osrc = (const float4*)(offs + ((size_t)(b * HW + p0)) * NOFF);
        float4* odst = (float4*)offs_s;
        for (int i = tid; i < 1152; i += 256) odst[i] = osrc[i];
    }

    ull acc[8][4];
#pragma unroll
    for (int i = 0; i < 8; i++)
#pragma unroll
        for (int j = 0; j < 4; j++) acc[i][j] = 0ull;

    int txo = tx * 4;
    const float* sbase = samp + ty * SAMP_ST;

    for (int ck = 0; ck < 9; ck++) {
        __syncthreads();   // previous tap's samples consumed / offs_s ready (ck=0)

        // stage weights for this tap
        {
            const float4* src = (const float4*)(wt + ck * 4096);
            float4* dst = (float4*)wsb;
#pragma unroll
            for (int r = 0; r < 4; r++) dst[tid + 256 * r] = src[tid + 256 * r];
        }
        // fill samples for this tap: each warp 32 px, lane = channel pair
        {
            int kdy = ck / 3 - 1, kdx = ck % 3 - 1;
            int c2 = 2 * lane;
#pragma unroll 4
            for (int px = warp; px < 256; px += 8) {
                int p = p0 + px;
                int h = p / WW, w = p - h * WW;
                float2 od = *(const float2*)(offs_s + px * NOFF + 2 * ck);
                float py  = (float)(h + kdy) + od.x;
                float pxf = (float)(w + kdx) + od.y;
                float fy = floorf(py), fx = floorf(pxf);
                int y0 = (int)fy, x0 = (int)fx;
                float wy = py - fy, wx = pxf - fx;
                bool vy0 = (unsigned)y0 < (unsigned)HH;
                bool vy1 = (unsigned)(y0 + 1) < (unsigned)HH;
                bool vx0 = (unsigned)x0 < (unsigned)WW;
                bool vx1 = (unsigned)(x0 + 1) < (unsigned)WW;
                const float* base = xt_b + ((ptrdiff_t)y0 * WW + x0) * CC + c2;
                float2 z = make_float2(0.f, 0.f);
                float2 g00 = (vy0 && vx0) ? *(const float2*)(base)              : z;
                float2 g01 = (vy0 && vx1) ? *(const float2*)(base + CC)         : z;
                float2 g10 = (vy1 && vx0) ? *(const float2*)(base + WW*CC)      : z;
                float2 g11 = (vy1 && vx1) ? *(const float2*)(base + WW*CC + CC) : z;
                float w00 = (1.f - wy) * (1.f - wx);
                float w01 = (1.f - wy) * wx;
                float w10 = wy * (1.f - wx);
                float w11 = wy * wx;
                float sx = g00.x * w00 + g01.x * w01 + g10.x * w10 + g11.x * w11;
                float sy = g00.y * w00 + g01.y * w01 + g10.y * w10 + g11.y * w11;
                *(float2*)(samp + px * SAMP_ST + c2) = make_float2(sx, sy);
            }
        }
        __syncthreads();

        // GEMM over this tap's 64 channels
#pragma unroll 2
        for (int cc = 0; cc < 64; cc += 4) {
            float4 sv[8];
#pragma unroll
            for (int i = 0; i < 8; i++)
                sv[i] = *(const float4*)(sbase + i * (32 * SAMP_ST) + cc);
#pragma unroll
            for (int r = 0; r < 4; r++) {
                float4 wa = *(const float4*)(wsb + (cc + r) * 64 + txo);
                float4 wc = *(const float4*)(wsb + (cc + r) * 64 + txo + 32);
                ull w0, w1, w2, w3;
                PACKF2(w0, wa.x, wa.y);
                PACKF2(w1, wa.z, wa.w);
                PACKF2(w2, wc.x, wc.y);
                PACKF2(w3, wc.z, wc.w);
#pragma unroll
                for (int i = 0; i < 8; i++) {
                    float s = (r == 0) ? sv[i].x : (r == 1) ? sv[i].y :
                              (r == 2) ? sv[i].z : sv[i].w;
                    ull ss;
                    PACKF2(ss, s, s);
                    FMA2(acc[i][0], ss, w0, acc[i][0]);
                    FMA2(acc[i][1], ss, w1, acc[i][1]);
                    FMA2(acc[i][2], ss, w2, acc[i][2]);
                    FMA2(acc[i][3], ss, w3, acc[i][3]);
                }
            }
        }
    }

    // epilogue: outs {txo..txo+3} and {txo+32..txo+35}, px = p0 + ty + 32*i
    float2 bA = *(const float2*)(cb + txo);
    float2 bB = *(const float2*)(cb + txo + 2);
    float2 bC = *(const float2*)(cb + txo + 32);
    float2 bD = *(const float2*)(cb + txo + 34);
#pragma unroll
    for (int i = 0; i < 8; i++) {
        int p = p0 + ty + 32 * i;
        float lo, hi;
        float* ob0 = out + (size_t)(b * OO + txo) * HW + p;
        UNPKF2(lo, hi, acc[i][0]);
        ob0[0]      = lo + bA.x;  ob0[HW]     = hi + bA.y;
        UNPKF2(lo, hi, acc[i][1]);
        ob0[2 * HW] = lo + bB.x;  ob0[3 * HW] = hi + bB.y;
        float* ob1 = ob0 + (size_t)32 * HW;
        UNPKF2(lo, hi, acc[i][2]);
        ob1[0]      = lo + bC.x;  ob1[HW]     = hi + bC.y;
        UNPKF2(lo, hi, acc[i][3]);
        ob1[2 * HW] = lo + bD.x;  ob1[3 * HW] = hi + bD.y;
    }
}

// ---------------- launch ------------------------------------------------------
extern "C" void kernel_launch(void* const* d_in, const int* in_sizes, int n_in,
                              void* d_out, int out_size) {
    const float* x  = (const float*)d_in[0];
    const float* ow = (const float*)d_in[1];
    const float* ob = (const float*)d_in[2];
    const float* cw = (const float*)d_in[3];
    const float* cb = (const float*)d_in[4];
    float* out = (float*)d_out;

    float *xt, *offs, *wt, *owt;
    cudaGetSymbolAddress((void**)&xt,   g_xt);
    cudaGetSymbolAddress((void**)&offs, g_offs);
    cudaGetSymbolAddress((void**)&wt,   g_wt);
    cudaGetSymbolAddress((void**)&owt,  g_owt);

    cudaFuncSetAttribute(fused_deform_kernel,
                         cudaFuncAttributeMaxDynamicSharedMemorySize, SMEM_FUSED);

    transpose_x_kernel<<<4608, 256>>>(x, xt);
    build_weights_kernel<<<144, 256>>>(cw, ow, wt, owt);
    offset_conv_kernel<<<288, 256>>>(x, owt, ob, offs);
    fused_deform_kernel<<<288, 256, SMEM_FUSED>>>(xt, offs, wt, cb, out);
}